// round 1
// baseline (speedup 1.0000x reference)
#include <cuda_runtime.h>

// Pooling_83141976916902: global-add-pool with a degenerate softmax gate.
//   logits = x@W + b  -> softmax over axis of size 1 -> all ones
//   => out[g, :] = sum_{n : batch[n]==g} x[n, :]
// batch is SORTED, N = 1e6, C = 128, G = out_size / C.
//
// Strategy: warp-per-chunk register accumulation over contiguous nodes,
// float4 per lane (lane l owns channels 4l..4l+3), flush via atomicAdd on
// segment change. Unroll-8 independent loads for memory-level parallelism.

#define CCH 128   // channels

__global__ void zero_out_kernel(float* __restrict__ out, int n) {
    int i = blockIdx.x * blockDim.x + threadIdx.x;
    if (i < n) out[i] = 0.0f;
}

__device__ __forceinline__ int seg_at(const void* batch, long long n, bool is64) {
    if (is64) return (int)__ldg(((const long long*)batch) + n);
    return __ldg(((const int*)batch) + n);
}

__global__ __launch_bounds__(256) void seg_sum_kernel(
    const float4* __restrict__ x4,     // [N * 32] float4  (N rows of 128 ch)
    const void*   __restrict__ batch,  // int32 or int64, sorted
    float*        __restrict__ out,    // [G * 128]
    int N, int nwarp_total)
{
    // dtype probe: odd int32 index mid-array. int64 data -> high word == 0.
    // int32 data -> a sorted segment id ~ G/2 != 0. In-bounds either way.
    const int probe = ((N >> 1) | 1);
    const bool is64 = (__ldg(((const int*)batch) + probe) == 0);

    const int gwarp = (int)((blockIdx.x * blockDim.x + threadIdx.x) >> 5);
    const int lane  = threadIdx.x & 31;

    const long long chunk = ((long long)N + nwarp_total - 1) / nwarp_total;
    long long n0 = (long long)gwarp * chunk;
    long long n1 = n0 + chunk;
    if (n1 > N) n1 = N;
    if (n0 >= n1) return;

    float4 acc = make_float4(0.f, 0.f, 0.f, 0.f);
    int cur = seg_at(batch, n0, is64);

    long long n = n0;
    constexpr int U = 8;

    for (; n + U <= n1; n += U) {
        float4 v[U];
        int    s[U];
        #pragma unroll
        for (int u = 0; u < U; u++)
            v[u] = __ldg(&x4[(n + u) * 32 + lane]);   // 8 independent loads: MLP
        #pragma unroll
        for (int u = 0; u < U; u++)
            s[u] = seg_at(batch, n + u, is64);
        #pragma unroll
        for (int u = 0; u < U; u++) {
            if (s[u] != cur) {
                float* o = out + (long long)cur * CCH + lane * 4;
                atomicAdd(o + 0, acc.x);
                atomicAdd(o + 1, acc.y);
                atomicAdd(o + 2, acc.z);
                atomicAdd(o + 3, acc.w);
                acc = make_float4(0.f, 0.f, 0.f, 0.f);
                cur = s[u];
            }
            acc.x += v[u].x; acc.y += v[u].y;
            acc.z += v[u].z; acc.w += v[u].w;
        }
    }
    for (; n < n1; n++) {
        float4 v = __ldg(&x4[n * 32 + lane]);
        int s = seg_at(batch, n, is64);
        if (s != cur) {
            float* o = out + (long long)cur * CCH + lane * 4;
            atomicAdd(o + 0, acc.x);
            atomicAdd(o + 1, acc.y);
            atomicAdd(o + 2, acc.z);
            atomicAdd(o + 3, acc.w);
            acc = make_float4(0.f, 0.f, 0.f, 0.f);
            cur = s;
        }
        acc.x += v.x; acc.y += v.y; acc.z += v.z; acc.w += v.w;
    }
    // final flush
    {
        float* o = out + (long long)cur * CCH + lane * 4;
        atomicAdd(o + 0, acc.x);
        atomicAdd(o + 1, acc.y);
        atomicAdd(o + 2, acc.z);
        atomicAdd(o + 3, acc.w);
    }
}

extern "C" void kernel_launch(void* const* d_in, const int* in_sizes, int n_in,
                              void* d_out, int out_size) {
    const float* x     = (const float*)d_in[0];   // [N, 128] fp32
    const void*  batch = d_in[1];                 // [N] int32 or int64, sorted
    // d_in[2] (W) and d_in[3] (b) are mathematically dead: softmax over a
    // size-1 axis is identically 1.
    float* out = (float*)d_out;

    const int N = in_sizes[1];                    // node count

    // d_out is poisoned to 0xAA; zero it (same stream -> ordered).
    zero_out_kernel<<<(out_size + 255) / 256, 256>>>(out, out_size);

    const int blocks = 148 * 8;                   // one full wave at 256 thr
    const int nwarps = blocks * (256 / 32);
    seg_sum_kernel<<<blocks, 256>>>((const float4*)x, batch, out, N, nwarps);
}

// round 2
// speedup vs baseline: 1.0131x; 1.0131x over previous
#include <cuda_runtime.h>

// Pooling_83141976916902: degenerate softmax gate => pure sorted segment-sum.
//   out[g, :] = sum_{n : batch[n]==g} x[n, :],  N=1e6, C=128, G=out/128.
//
// R2 changes vs R1 (91.8us, DRAM 77.6%, occ 51.5%):
//  - 128-thread blocks, grid = 148*10: single wave at regs<=51 (was 1.6 waves)
//  - seg-id loads moved inside process loop (L1 broadcast hit) -> lower regs
//  - red.global.add.v4.f32 flush (1 instr instead of 4 atomicAdd)

#define CCH 128

__global__ void zero_out_kernel(float4* __restrict__ out, int n4) {
    int i = blockIdx.x * blockDim.x + threadIdx.x;
    if (i < n4) out[i] = make_float4(0.f, 0.f, 0.f, 0.f);
}

__device__ __forceinline__ int seg_at(const void* batch, long long n, bool is64) {
    if (is64) return (int)__ldg(((const long long*)batch) + n);
    return __ldg(((const int*)batch) + n);
}

__device__ __forceinline__ void red_add_v4(float* addr, float4 v) {
    asm volatile("red.global.add.v4.f32 [%0], {%1, %2, %3, %4};"
                 :: "l"(addr), "f"(v.x), "f"(v.y), "f"(v.z), "f"(v.w)
                 : "memory");
}

__global__ __launch_bounds__(128) void seg_sum_kernel(
    const float4* __restrict__ x4,     // N rows x 32 float4
    const void*   __restrict__ batch,  // int32 or int64, sorted
    float*        __restrict__ out,    // [G * 128]
    int N, int nwarp_total)
{
    // dtype probe: odd int32 index mid-array. int64 -> high word == 0;
    // int32 -> sorted mid segment id != 0. In-bounds either way.
    const int probe = ((N >> 1) | 1);
    const bool is64 = (__ldg(((const int*)batch) + probe) == 0);

    const int gwarp = (int)((blockIdx.x * blockDim.x + threadIdx.x) >> 5);
    const int lane  = threadIdx.x & 31;

    const long long chunk = ((long long)N + nwarp_total - 1) / nwarp_total;
    long long n0 = (long long)gwarp * chunk;
    long long n1 = n0 + chunk;
    if (n1 > N) n1 = N;
    if (n0 >= n1) return;

    float4 acc = make_float4(0.f, 0.f, 0.f, 0.f);
    int cur = seg_at(batch, n0, is64);

    long long n = n0;
    constexpr int U = 8;

    for (; n + U <= n1; n += U) {
        float4 v[U];
        #pragma unroll
        for (int u = 0; u < U; u++)
            v[u] = __ldg(&x4[(n + u) * 32 + lane]);   // U independent DRAM loads
        #pragma unroll
        for (int u = 0; u < U; u++) {
            int s = seg_at(batch, n + u, is64);       // L1 broadcast hit
            if (s != cur) {
                red_add_v4(out + (long long)cur * CCH + lane * 4, acc);
                acc = make_float4(0.f, 0.f, 0.f, 0.f);
                cur = s;
            }
            acc.x += v[u].x; acc.y += v[u].y;
            acc.z += v[u].z; acc.w += v[u].w;
        }
    }
    for (; n < n1; n++) {
        float4 v = __ldg(&x4[n * 32 + lane]);
        int s = seg_at(batch, n, is64);
        if (s != cur) {
            red_add_v4(out + (long long)cur * CCH + lane * 4, acc);
            acc = make_float4(0.f, 0.f, 0.f, 0.f);
            cur = s;
        }
        acc.x += v.x; acc.y += v.y; acc.z += v.z; acc.w += v.w;
    }
    red_add_v4(out + (long long)cur * CCH + lane * 4, acc);
}

extern "C" void kernel_launch(void* const* d_in, const int* in_sizes, int n_in,
                              void* d_out, int out_size) {
    const float* x     = (const float*)d_in[0];   // [N, 128] fp32
    const void*  batch = d_in[1];                 // [N] int32/int64 sorted
    float* out = (float*)d_out;

    const int N = in_sizes[1];

    zero_out_kernel<<<(out_size / 4 + 255) / 256, 256>>>((float4*)out, out_size / 4);

    const int blocks = 148 * 10;                  // single wave (reg limit >= 11/SM)
    const int nwarps = blocks * (128 / 32);
    seg_sum_kernel<<<blocks, 128>>>((const float4*)x, batch, out, N, nwarps);
}